// round 1
// baseline (speedup 1.0000x reference)
#include <cuda_runtime.h>
#include <math.h>

#define NN 50000
#define NE 800000
#define DD 64
#define GG 512
#define CHUNK 512
#define NCHUNK ((NN + CHUNK - 1) / CHUNK)   // 98

// -------- scratch (device globals; no allocation allowed) --------
__device__ float g_bufA[NN * DD];
__device__ float g_bufB[NN * DD];
__device__ float g_agg[NN * DD];
__device__ int   g_cnt[NN];
__device__ int   g_rowptr[NN + 1];
__device__ int   g_cursor[NN];
__device__ int   g_csr[NE];
__device__ int   g_chunksum[NCHUNK];
__device__ float g_pool[GG * DD];
__device__ float g_pcnt[GG];

__device__ __forceinline__ const float* pick_in(int sel, const float* x) {
    return sel == 0 ? x : (sel == 1 ? g_bufA : g_bufB);
}

// -------- CSR build --------
__global__ void k_zero() {
    int i = blockIdx.x * blockDim.x + threadIdx.x;
    if (i < NN) g_cnt[i] = 0;
    if (i < GG) g_pcnt[i] = 0.f;
    if (i < GG * DD) g_pool[i] = 0.f;
}

__global__ void k_count(const int* __restrict__ dst) {
    int e = blockIdx.x * blockDim.x + threadIdx.x;
    if (e < NE) atomicAdd(&g_cnt[dst[e]], 1);
}

__global__ void k_scan1() {
    __shared__ int s[CHUNK];
    int i = blockIdx.x * CHUNK + threadIdx.x;
    s[threadIdx.x] = (i < NN) ? g_cnt[i] : 0;
    __syncthreads();
    for (int off = CHUNK / 2; off > 0; off >>= 1) {
        if (threadIdx.x < off) s[threadIdx.x] += s[threadIdx.x + off];
        __syncthreads();
    }
    if (threadIdx.x == 0) g_chunksum[blockIdx.x] = s[0];
}

__global__ void k_scan2() {
    if (threadIdx.x == 0) {
        int run = 0;
        for (int i = 0; i < NCHUNK; i++) {
            int t = g_chunksum[i];
            g_chunksum[i] = run;
            run += t;
        }
        g_rowptr[NN] = run;   // == NE
    }
}

__global__ void k_scan3() {
    __shared__ int s[CHUNK];
    int i = blockIdx.x * CHUNK + threadIdx.x;
    int v = (i < NN) ? g_cnt[i] : 0;
    s[threadIdx.x] = v;
    __syncthreads();
    for (int off = 1; off < CHUNK; off <<= 1) {
        int t = (threadIdx.x >= off) ? s[threadIdx.x - off] : 0;
        __syncthreads();
        s[threadIdx.x] += t;
        __syncthreads();
    }
    if (i < NN) {
        int excl = g_chunksum[blockIdx.x] + s[threadIdx.x] - v;
        g_rowptr[i] = excl;
        g_cursor[i] = excl;
    }
}

__global__ void k_fill(const int* __restrict__ src, const int* __restrict__ dst) {
    int e = blockIdx.x * blockDim.x + threadIdx.x;
    if (e < NE) {
        int pos = atomicAdd(&g_cursor[dst[e]], 1);
        g_csr[pos] = src[e];
    }
}

// -------- per-layer edge aggregation: agg[i] = sum_{j in N(i)} h[j] --------
__global__ void k_agg(const float* __restrict__ x, int sel) {
    const float* h = pick_in(sel, x);
    int node = blockIdx.x * 4 + (threadIdx.x >> 6);
    int d = threadIdx.x & 63;
    if (node >= NN) return;
    int s0 = g_rowptr[node];
    int s1 = g_rowptr[node + 1];
    float acc = 0.f;
    for (int e = s0; e < s1; e++) {
        int s = __ldg(&g_csr[e]);
        acc += __ldg(&h[s * DD + d]);
    }
    g_agg[node * DD + d] = acc;
}

// -------- fused layer GEMM: out = relu(agg@Wrel^T + b + h@Wroot^T (+ h)) ----
// 64x64 node/out tile per block, K=128 done as two K=64 phases.
// Shared staging k-major with XOR-of-(k>>2) swizzle on the 4-float column
// group -> conflict-free compute loads, 2-way store conflicts.
__global__ void k_gemm(const float* __restrict__ x, int insel, int outsel,
                       const float* __restrict__ wrel,
                       const float* __restrict__ wroot,
                       const float* __restrict__ brel, int residual) {
    const float* hin = pick_in(insel, x);
    float* hout = (outsel == 1) ? g_bufA : g_bufB;

    __shared__ float As[64 * 64];
    __shared__ float Bs[64 * 64];

    int tid = threadIdx.x;
    int tx = tid & 15;        // output group (4 cols)
    int ty = tid >> 4;        // node group (4 rows)
    int m0 = blockIdx.x * 64;

    float acc[4][4];
#pragma unroll
    for (int i = 0; i < 4; i++)
#pragma unroll
        for (int j = 0; j < 4; j++) acc[i][j] = 0.f;

#pragma unroll
    for (int phase = 0; phase < 2; phase++) {
        const float* A = phase ? hin : g_agg;
        const float* W = phase ? wroot : wrel;

        // stage A tile (transpose to k-major, swizzled)
#pragma unroll
        for (int it = 0; it < 4; it++) {
            int m = it * 16 + ty;
            int kq = tx;
            float4 v = make_float4(0.f, 0.f, 0.f, 0.f);
            if (m0 + m < NN) v = *(const float4*)&A[(m0 + m) * DD + kq * 4];
            int col = ((((m >> 2) ^ kq) & 15) << 2) | (m & 3);
            As[(kq * 4 + 0) * 64 + col] = v.x;
            As[(kq * 4 + 1) * 64 + col] = v.y;
            As[(kq * 4 + 2) * 64 + col] = v.z;
            As[(kq * 4 + 3) * 64 + col] = v.w;
        }
        // stage B tile: Bs[k][j] = W[j][k]
#pragma unroll
        for (int it = 0; it < 4; it++) {
            int j = it * 16 + ty;
            int kq = tx;
            float4 v = *(const float4*)&W[j * DD + kq * 4];
            int col = ((((j >> 2) ^ kq) & 15) << 2) | (j & 3);
            Bs[(kq * 4 + 0) * 64 + col] = v.x;
            Bs[(kq * 4 + 1) * 64 + col] = v.y;
            Bs[(kq * 4 + 2) * 64 + col] = v.z;
            Bs[(kq * 4 + 3) * 64 + col] = v.w;
        }
        __syncthreads();

#pragma unroll
        for (int k = 0; k < 64; k++) {
            int sw = (k >> 2) & 15;
            float4 a = *(const float4*)&As[k * 64 + ((ty ^ sw) << 2)];
            float4 b = *(const float4*)&Bs[k * 64 + ((tx ^ sw) << 2)];
            float av[4] = {a.x, a.y, a.z, a.w};
            float bv[4] = {b.x, b.y, b.z, b.w};
#pragma unroll
            for (int i = 0; i < 4; i++)
#pragma unroll
                for (int j = 0; j < 4; j++) acc[i][j] += av[i] * bv[j];
        }
        __syncthreads();
    }

    float bias[4];
#pragma unroll
    for (int jj = 0; jj < 4; jj++) bias[jj] = __ldg(&brel[tx * 4 + jj]);

#pragma unroll
    for (int i = 0; i < 4; i++) {
        int m = m0 + ty * 4 + i;
        if (m < NN) {
            float v0 = acc[i][0] + bias[0];
            float v1 = acc[i][1] + bias[1];
            float v2 = acc[i][2] + bias[2];
            float v3 = acc[i][3] + bias[3];
            if (residual) {
                float4 h4 = *(const float4*)&hin[m * DD + tx * 4];
                v0 += h4.x; v1 += h4.y; v2 += h4.z; v3 += h4.w;
            }
            float4 r;
            r.x = fmaxf(v0, 0.f);
            r.y = fmaxf(v1, 0.f);
            r.z = fmaxf(v2, 0.f);
            r.w = fmaxf(v3, 0.f);
            *(float4*)&hout[m * DD + tx * 4] = r;
        }
    }
}

// -------- mean pool over graph ids --------
__global__ void k_pool(const float* __restrict__ x, int sel,
                       const int* __restrict__ batch) {
    const float* h = pick_in(sel, x);
    int node = blockIdx.x * 4 + (threadIdx.x >> 6);
    int d = threadIdx.x & 63;
    if (node >= NN) return;
    int b = batch[node];
    atomicAdd(&g_pool[b * DD + d], h[node * DD + d]);
    if (d == 0) atomicAdd(&g_pcnt[b], 1.f);
}

// -------- final linear + softmax, one block per graph --------
__global__ void k_final(const float* __restrict__ lin_w,
                        const float* __restrict__ lin_b,
                        float* __restrict__ out) {
    __shared__ float sw[64 * 65];   // transposed, padded: sw[k*65 + j]
    __shared__ float p[64];
    __shared__ float red[64];
    int g = blockIdx.x;
    int j = threadIdx.x;

    // load lin_w coalesced, store transposed (conflict-free both ways)
    for (int r = 0; r < 64; r++) sw[j * 65 + r] = lin_w[r * 64 + j];

    float cnt = fmaxf(g_pcnt[g], 1.f);
    p[j] = g_pool[g * DD + j] / cnt;
    __syncthreads();

    float acc = lin_b[j];
#pragma unroll
    for (int k = 0; k < 64; k++) acc += p[k] * sw[k * 65 + j];

    red[j] = acc;
    __syncthreads();
    for (int s = 32; s > 0; s >>= 1) {
        if (j < s) red[j] = fmaxf(red[j], red[j + s]);
        __syncthreads();
    }
    float mx = red[0];
    __syncthreads();
    float e = expf(acc - mx);
    red[j] = e;
    __syncthreads();
    for (int s = 32; s > 0; s >>= 1) {
        if (j < s) red[j] += red[j + s];
        __syncthreads();
    }
    out[g * DD + j] = e / red[0];
}

extern "C" void kernel_launch(void* const* d_in, const int* in_sizes, int n_in,
                              void* d_out, int out_size) {
    const float* x      = (const float*)d_in[0];
    const int*   ei     = (const int*)d_in[1];
    const int*   batch  = (const int*)d_in[2];
    const float* rel_w  = (const float*)d_in[3];
    const float* rel_b  = (const float*)d_in[4];
    const float* root_w = (const float*)d_in[5];
    const float* lin_w  = (const float*)d_in[6];
    const float* lin_b  = (const float*)d_in[7];
    float* out = (float*)d_out;

    const int* src = ei;
    const int* dst = ei + NE;

    k_zero<<<(NN + 255) / 256, 256>>>();
    k_count<<<(NE + 255) / 256, 256>>>(dst);
    k_scan1<<<NCHUNK, CHUNK>>>();
    k_scan2<<<1, 32>>>();
    k_scan3<<<NCHUNK, CHUNK>>>();
    k_fill<<<(NE + 255) / 256, 256>>>(src, dst);

    int insel = 0;
    for (int l = 0; l < 5; l++) {
        int outsel = (insel == 1) ? 2 : 1;
        k_agg<<<(NN + 3) / 4, 256>>>(x, insel);
        k_gemm<<<(NN + 63) / 64, 256>>>(x, insel, outsel,
                                        rel_w + l * DD * DD,
                                        root_w + l * DD * DD,
                                        rel_b + l * DD,
                                        (l >= 3) ? 1 : 0);
        insel = outsel;
    }

    k_pool<<<(NN + 3) / 4, 256>>>(x, insel, batch);
    k_final<<<GG, DD>>>(lin_w, lin_b, out);
}